// round 15
// baseline (speedup 1.0000x reference)
#include <cuda_runtime.h>

#define T_LEN 1024
#define B_SZ  128
#define D_IN  32
#define H_DIM 64
#define W_DIM 128
#define C_DIM 33     // D_IN + 1
#define O_DIM 2112   // H_DIM * C_DIM
#define O_MAIN 2048  // main (uniform) part of layer-3 outputs
#define BA    2      // batches per CTA
#define NCTA  (B_SZ / BA)   // 64
#define NTHR  256

// Transposed copy of vW2 rows [0, 2048): g_vW2T[k * 2048 + o] = vW2[o * 128 + k]
__device__ float g_vW2T[W_DIM * O_MAIN];

__global__ void cde_transpose_kernel(const float* __restrict__ vW2) {
    int idx = blockIdx.x * blockDim.x + threadIdx.x;
    if (idx < W_DIM * O_MAIN) {
        int k = idx >> 11;     // / 2048
        int o = idx & 2047;
        g_vW2T[idx] = vW2[o * W_DIM + k];
    }
}

typedef unsigned long long u64;

struct __align__(16) Smem {
    float vW0p[W_DIM * 66];   // [j][paired w[1..64]]; stride 66 -> LDS.64 conflict-free
    float vW0c[W_DIM];        // w[j][0] (the t column)
    float vW1[W_DIM * 130];   // [j][k], stride 130 -> LDS.64 conflict-free
    float vb0[W_DIM];
    float vb1[W_DIM];
    float vb2[O_DIM];
    float vbuf[BA][O_DIM];    // v (tanh outputs), per batch
    float z1[BA][W_DIM];
    float z2[BA][W_DIM];      // plain copy (for tail)
    u64   z2d[W_DIM][2];      // [k][b] = (z_b, z_b) pre-duplicated for FFMA2
    float yhat1[BA][H_DIM];
    float dxv[2][BA][36];     // parity double-buffered dx
    float red[BA][H_DIM];
};

__device__ __forceinline__ void ffma2(u64& d, u64 a, u64 b) {
    // d.lo += a.lo*b.lo ; d.hi += a.hi*b.hi  (packed fp32x2 FMA, sm_100+)
    asm("fma.rn.f32x2 %0, %1, %2, %0;" : "+l"(d) : "l"(a), "l"(b));
}
__device__ __forceinline__ u64 pack2(float x, float y) {
    u64 r;
    asm("mov.b64 %0, {%1, %2};" : "=l"(r) : "f"(x), "f"(y));
    return r;
}
__device__ __forceinline__ float2 unpack2(u64 v) {
    float2 r;
    asm("mov.b64 {%0, %1}, %2;" : "=f"(r.x), "=f"(r.y) : "l"(v));
    return r;
}

__device__ __forceinline__ float lipswish_f(float x) {
    float sg = __fdividef(1.0f, 1.0f + __expf(-x));
    return 0.909f * x * sg;
}
__device__ __forceinline__ float tanh_f(float x) {
    float e = __expf(2.0f * x);
    return 1.0f - __fdividef(2.0f, e + 1.0f);
}

// vbuf = tanh(vW2 @ lipswish(vW1 @ lipswish(vW0 @ [t, yhat1] + vb0) + vb1) + vb2)
// for both batches. 256 threads. Layer-3 uses a 3-buffer x 4-k software pipeline.
__device__ __forceinline__ void vf_eval(Smem* sm, int tid, float t1,
                                        const float* __restrict__ vW2) {
    const int bb = tid >> 7;
    const int j  = tid & 127;

    // ---- layer 1: (65 -> 128), paired FFMA2 over the 64 yh inputs ----
    {
        const u64* wp = (const u64*)&sm->vW0p[j * 66];
        const u64* yp = (const u64*)sm->yhat1[bb];
        u64 acc[4] = {0ull, 0ull, 0ull, 0ull};
        #pragma unroll
        for (int p = 0; p < 32; p++) ffma2(acc[p & 3], wp[p], yp[p]);
        float2 s0 = unpack2(acc[0]), s1 = unpack2(acc[1]);
        float2 s2 = unpack2(acc[2]), s3 = unpack2(acc[3]);
        float a = sm->vb0[j] + t1 * sm->vW0c[j]
                + ((s0.x + s0.y) + (s1.x + s1.y))
                + ((s2.x + s2.y) + (s3.x + s3.y));
        sm->z1[bb][j] = lipswish_f(a);
    }
    __syncthreads();

    // ---- layer 2: (128 -> 128), paired ----
    {
        const u64* wp = (const u64*)&sm->vW1[j * 130];
        const u64* zp = (const u64*)sm->z1[bb];
        u64 acc[4] = {0ull, 0ull, 0ull, 0ull};
        #pragma unroll
        for (int p = 0; p < 64; p++) ffma2(acc[p & 3], wp[p], zp[p]);
        float2 s0 = unpack2(acc[0]), s1 = unpack2(acc[1]);
        float2 s2 = unpack2(acc[2]), s3 = unpack2(acc[3]);
        float a = sm->vb1[j]
                + ((s0.x + s0.y) + (s1.x + s1.y))
                + ((s2.x + s2.y) + (s3.x + s3.y));
        float v = lipswish_f(a);
        sm->z2[bb][j]  = v;            // for tail
        sm->z2d[j][bb] = pack2(v, v);  // pre-duplicated for main loop
    }
    __syncthreads();

    // ---- layer 3 main: two passes of (4 outputs x 2 batches), 3-buf x 4-k pipeline ----
    #pragma unroll
    for (int p = 0; p < 2; p++) {
        const float* wbase = g_vW2T + 4 * tid + p * 1024;
        u64 acc0 = 0ull, acc1 = 0ull, acc2 = 0ull, acc3 = 0ull;
        ulonglong2 wbuf[3][4];   // 48 registers of weight buffer
        #pragma unroll
        for (int c = 0; c < 4; c++)
            wbuf[0][c] = *(const ulonglong2*)(wbase + (size_t)c * O_MAIN);
        #pragma unroll
        for (int c = 0; c < 4; c++)
            wbuf[1][c] = *(const ulonglong2*)(wbase + (size_t)(4 + c) * O_MAIN);
        #pragma unroll
        for (int ch = 0; ch < 32; ch++) {
            const int cur = ch % 3;
            const int nxt = (ch + 2) % 3;
            if (ch < 30) {
                #pragma unroll
                for (int c = 0; c < 4; c++)
                    wbuf[nxt][c] = *(const ulonglong2*)(wbase + (size_t)((ch + 2) * 4 + c) * O_MAIN);
            }
            #pragma unroll
            for (int c = 0; c < 4; c++) {
                const int k = ch * 4 + c;
                u64 zz0 = sm->z2d[k][0];   // LDS.64 broadcast
                u64 zz1 = sm->z2d[k][1];
                ulonglong2 w = wbuf[cur][c];
                ffma2(acc0, w.x, zz0); ffma2(acc1, w.y, zz0);
                ffma2(acc2, w.x, zz1); ffma2(acc3, w.y, zz1);
            }
        }
        const int o = 4 * tid + p * 1024;
        float b0v = sm->vb2[o + 0], b1v = sm->vb2[o + 1];
        float b2v = sm->vb2[o + 2], b3v = sm->vb2[o + 3];
        {
            float2 r0 = unpack2(acc0), r1 = unpack2(acc1);
            float4 res;
            res.x = tanh_f(r0.x + b0v);
            res.y = tanh_f(r0.y + b1v);
            res.z = tanh_f(r1.x + b2v);
            res.w = tanh_f(r1.y + b3v);
            *(float4*)&sm->vbuf[0][o] = res;
        }
        {
            float2 r0 = unpack2(acc2), r1 = unpack2(acc3);
            float4 res;
            res.x = tanh_f(r0.x + b0v);
            res.y = tanh_f(r0.y + b1v);
            res.z = tanh_f(r1.x + b2v);
            res.w = tanh_f(r1.y + b3v);
            *(float4*)&sm->vbuf[1][o] = res;
        }
    }

    // ---- layer 3 tail: outputs [2048, 2112), 8 warps x 8 outputs ----
    {
        const int w = tid >> 5, lane = tid & 31;
        float4 zz0 = *(const float4*)&sm->z2[0][4 * lane];
        float4 zz1 = *(const float4*)&sm->z2[1][4 * lane];
        #pragma unroll
        for (int i = 0; i < 8; i++) {
            int o = O_MAIN + w * 8 + i;
            float4 wv = *(const float4*)(vW2 + (size_t)o * W_DIM + 4 * lane);
            float a0 = wv.x * zz0.x + wv.y * zz0.y + wv.z * zz0.z + wv.w * zz0.w;
            float a1 = wv.x * zz1.x + wv.y * zz1.y + wv.z * zz1.z + wv.w * zz1.w;
            #pragma unroll
            for (int off = 16; off; off >>= 1) {
                a0 += __shfl_xor_sync(0xffffffffu, a0, off);
                a1 += __shfl_xor_sync(0xffffffffu, a1, off);
            }
            if (lane == 0) {
                float b = sm->vb2[o];
                sm->vbuf[0][o] = tanh_f(a0 + b);
                sm->vbuf[1][o] = tanh_f(a1 + b);
            }
        }
    }
    __syncthreads();
}

__global__ void __launch_bounds__(NTHR, 1) cde_kernel(
    const float* __restrict__ ts,  const float* __restrict__ ys,
    const float* __restrict__ iW0, const float* __restrict__ ib0,
    const float* __restrict__ iW1, const float* __restrict__ ib1,
    const float* __restrict__ iW2, const float* __restrict__ ib2,
    const float* __restrict__ vW0, const float* __restrict__ vb0,
    const float* __restrict__ vW1, const float* __restrict__ vb1,
    const float* __restrict__ vW2, const float* __restrict__ vb2,
    const float* __restrict__ rW,  const float* __restrict__ rb,
    float* __restrict__ out)
{
    extern __shared__ float smraw[];
    Smem* sm = reinterpret_cast<Smem*>(smraw);
    const int tid = threadIdx.x;
    const int b0  = blockIdx.x * BA;

    // ---- stage weights into smem ----
    for (int i = tid; i < W_DIM * 65; i += NTHR) {
        int j = i / 65, c = i % 65;
        if (c == 0) sm->vW0c[j] = vW0[i];
        else        sm->vW0p[j * 66 + (c - 1)] = vW0[i];
    }
    for (int i = tid; i < W_DIM * W_DIM; i += NTHR) {
        int j = i >> 7, k = i & 127;
        sm->vW1[j * 130 + k] = vW1[i];
    }
    if (tid < W_DIM) { sm->vb0[tid] = vb0[tid]; sm->vb1[tid] = vb1[tid]; }
    for (int i = tid; i < O_DIM; i += NTHR) sm->vb2[i] = vb2[i];

    // dx-owner thread mapping (valid when tid < BA*C_DIM = 66)
    const int myb = tid / C_DIM;
    const int myc = tid - myb * C_DIM;
    const bool dxo = (tid < BA * C_DIM);

    // initial x0 = [ts[0], ys[b,0,:]] into dxv[0]; cury lives in a register
    float cury_r = 0.f, pref_y = 0.f;
    if (dxo) {
        if (myc == 0) {
            sm->dxv[0][myb][0] = ts[0];
        } else {
            float v0 = ys[(size_t)(b0 + myb) * T_LEN * D_IN + (myc - 1)];
            sm->dxv[0][myb][myc] = v0;
            cury_r = v0;
            pref_y = __ldg(&ys[(size_t)(b0 + myb) * T_LEN * D_IN + D_IN + (myc - 1)]);  // t=1
        }
    }
    float pref_t = __ldg(&ts[1]);
    __syncthreads();

    // ---- initial MLP: relu(iW0 x + ib0) -> relu(iW1 . + ib1) -> iW2 . + ib2 ----
    {
        int bb = tid >> 7, j = tid & 127;
        float a = ib0[j];
        #pragma unroll
        for (int i = 0; i < C_DIM; i++) a += sm->dxv[0][bb][i] * iW0[j * C_DIM + i];
        sm->z1[bb][j] = fmaxf(a, 0.f);
    }
    __syncthreads();
    {
        int bb = tid >> 7, j = tid & 127;
        float a = ib1[j];
        #pragma unroll 8
        for (int k = 0; k < W_DIM; k++) a += sm->z1[bb][k] * iW1[j * W_DIM + k];
        sm->z2[bb][j] = fmaxf(a, 0.f);
    }
    __syncthreads();

    float y = 0.f, yhat = 0.f, sdot = 0.f;
    if (tid < BA * H_DIM) {
        int bb = tid >> 6, h = tid & 63;
        float a = ib2[h];
        #pragma unroll 8
        for (int k = 0; k < W_DIM; k++) a += sm->z2[bb][k] * iW2[h * W_DIM + k];
        y = a; yhat = a;
        sm->yhat1[bb][h] = a;
    }
    __syncthreads();

    // v0 = vf(ts[0], y0)
    vf_eval(sm, tid, ts[0], vW2);

    // ---- scan over 1023 steps ----
    float tprev = ts[0];
    for (int t = 1; t < T_LEN; t++) {
        const int par = t & 1;
        float t1 = pref_t;

        // dx = x[t] - x[t-1] into dxv[par] (prefetched values)
        if (dxo) {
            if (myc == 0) {
                sm->dxv[par][myb][0] = t1 - tprev;
            } else {
                float nv = pref_y;
                sm->dxv[par][myb][myc] = nv - cury_r;
                cury_r = nv;
            }
        }
        tprev = t1;

        // issue prefetch for step t+1 (covered by the rest of this step)
        if (t + 1 < T_LEN) {
            if (dxo && myc != 0)
                pref_y = __ldg(&ys[(size_t)(b0 + myb) * T_LEN * D_IN
                                   + (size_t)(t + 1) * D_IN + (myc - 1)]);
            pref_t = __ldg(&ts[t + 1]);
        }
        __syncthreads();

        // s = v . dx ; yhat1 = 2y - yhat + s
        if (tid < BA * H_DIM) {
            int bb = tid >> 6, h = tid & 63;
            const float* vp = &sm->vbuf[bb][h * C_DIM];
            const float* dp = sm->dxv[par][bb];
            float a = 0.f;
            #pragma unroll
            for (int c = 0; c < C_DIM; c++) a += vp[c] * dp[c];
            sdot = a;
            float yh1 = 2.f * y - yhat + a;
            yhat = yh1;
            sm->yhat1[bb][h] = yh1;
        }
        __syncthreads();

        // v1 = vf(t1, yhat1)  (overwrites vbuf; ends with __syncthreads)
        vf_eval(sm, tid, t1, vW2);

        // y += 0.5 * (s + v1 . dx)   — no trailing barrier (dxv parity-buffered)
        if (tid < BA * H_DIM) {
            int bb = tid >> 6, h = tid & 63;
            const float* vp = &sm->vbuf[bb][h * C_DIM];
            const float* dp = sm->dxv[par][bb];
            float a = 0.f;
            #pragma unroll
            for (int c = 0; c < C_DIM; c++) a += vp[c] * dp[c];
            y += 0.5f * (sdot + a);
        }
    }

    // ---- readout: out[b] = y . rW + rb ----
    __syncthreads();
    if (tid < BA * H_DIM) {
        int bb = tid >> 6, h = tid & 63;
        sm->red[bb][h] = y * rW[h];
    }
    __syncthreads();
    if (tid < BA) {
        float a = rb[0];
        #pragma unroll
        for (int h = 0; h < H_DIM; h++) a += sm->red[tid][h];
        out[b0 + tid] = a;
    }
}

extern "C" void kernel_launch(void* const* d_in, const int* in_sizes, int n_in,
                              void* d_out, int out_size) {
    (void)in_sizes; (void)n_in; (void)out_size;
    const float* ts  = (const float*)d_in[0];
    const float* ys  = (const float*)d_in[1];
    const float* iW0 = (const float*)d_in[2];
    const float* ib0 = (const float*)d_in[3];
    const float* iW1 = (const float*)d_in[4];
    const float* ib1 = (const float*)d_in[5];
    const float* iW2 = (const float*)d_in[6];
    const float* ib2 = (const float*)d_in[7];
    const float* vW0 = (const float*)d_in[8];
    const float* vb0 = (const float*)d_in[9];
    const float* vW1 = (const float*)d_in[10];
    const float* vb1 = (const float*)d_in[11];
    const float* vW2 = (const float*)d_in[12];
    const float* vb2 = (const float*)d_in[13];
    const float* rW  = (const float*)d_in[14];
    const float* rb  = (const float*)d_in[15];
    float* out = (float*)d_out;

    cudaFuncSetAttribute(cde_kernel, cudaFuncAttributeMaxDynamicSharedMemorySize,
                         (int)sizeof(Smem));

    cde_transpose_kernel<<<(W_DIM * O_MAIN + 255) / 256, 256>>>(vW2);
    cde_kernel<<<NCTA, NTHR, sizeof(Smem)>>>(
        ts, ys, iW0, ib0, iW1, ib1, iW2, ib2,
        vW0, vb0, vW1, vb1, vW2, vb2, rW, rb, out);
}

// round 16
// speedup vs baseline: 2.5886x; 2.5886x over previous
#include <cuda_runtime.h>

#define T_LEN 1024
#define B_SZ  128
#define D_IN  32
#define H_DIM 64
#define W_DIM 128
#define C_DIM 33     // D_IN + 1
#define O_DIM 2112   // H_DIM * C_DIM
#define O_MAIN 2048  // main (uniform) part of layer-3 outputs
#define BA    2      // batches per CTA
#define NCTA  (B_SZ / BA)   // 64
#define NTHR  256

// Transposed copy of vW2 rows [0, 2048): g_vW2T[k * 2048 + o] = vW2[o * 128 + k]
__device__ float g_vW2T[W_DIM * O_MAIN];

__global__ void cde_transpose_kernel(const float* __restrict__ vW2) {
    int idx = blockIdx.x * blockDim.x + threadIdx.x;
    if (idx < W_DIM * O_MAIN) {
        int k = idx >> 11;     // / 2048
        int o = idx & 2047;
        g_vW2T[idx] = vW2[o * W_DIM + k];
    }
}

typedef unsigned long long u64;

struct __align__(16) Smem {
    float vW0p[W_DIM * 66];   // [j][paired w[1..64]]; stride 66 -> LDS.64 conflict-free
    float vW0c[W_DIM];        // w[j][0] (the t column)
    float vW1[W_DIM * 130];   // [j][k], stride 130 -> LDS.64 conflict-free
    float vb0[W_DIM];
    float vb1[W_DIM];
    float vb2[O_DIM];
    float vbuf[BA][O_DIM];    // v (tanh outputs), per batch
    float z1[BA][W_DIM];
    float z2[BA][W_DIM];      // plain copy (for tail)
    u64   z2d[W_DIM][2];      // [k][b] = (z_b, z_b) pre-duplicated for FFMA2
    float yhat1[BA][H_DIM];
    float dxv[2][BA][36];     // parity double-buffered dx
    float red[BA][H_DIM];
};

__device__ __forceinline__ void ffma2(u64& d, u64 a, u64 b) {
    // d.lo += a.lo*b.lo ; d.hi += a.hi*b.hi  (packed fp32x2 FMA, sm_100+)
    asm("fma.rn.f32x2 %0, %1, %2, %0;" : "+l"(d) : "l"(a), "l"(b));
}
__device__ __forceinline__ u64 pack2(float x, float y) {
    u64 r;
    asm("mov.b64 %0, {%1, %2};" : "=l"(r) : "f"(x), "f"(y));
    return r;
}
__device__ __forceinline__ float2 unpack2(u64 v) {
    float2 r;
    asm("mov.b64 {%0, %1}, %2;" : "=f"(r.x), "=f"(r.y) : "l"(v));
    return r;
}

__device__ __forceinline__ float lipswish_f(float x) {
    float sg = __fdividef(1.0f, 1.0f + __expf(-x));
    return 0.909f * x * sg;
}
__device__ __forceinline__ float tanh_f(float x) {
    float e = __expf(2.0f * x);
    return 1.0f - __fdividef(2.0f, e + 1.0f);
}

// vbuf = tanh(vW2 @ lipswish(vW1 @ lipswish(vW0 @ [t, yhat1] + vb0) + vb1) + vb2)
// for both batches handled by this CTA. All 256 threads participate.
// Layer-3 main loop is the proven R6 form (plain unroll-2, ptxas-scheduled).
__device__ __forceinline__ void vf_eval(Smem* sm, int tid, float t1,
                                        const float* __restrict__ vW2) {
    const int bb = tid >> 7;
    const int j  = tid & 127;

    // ---- layer 1: (65 -> 128), paired FFMA2 over the 64 yh inputs ----
    {
        const u64* wp = (const u64*)&sm->vW0p[j * 66];
        const u64* yp = (const u64*)sm->yhat1[bb];
        u64 acc[4] = {0ull, 0ull, 0ull, 0ull};
        #pragma unroll
        for (int p = 0; p < 32; p++) ffma2(acc[p & 3], wp[p], yp[p]);
        float2 s0 = unpack2(acc[0]), s1 = unpack2(acc[1]);
        float2 s2 = unpack2(acc[2]), s3 = unpack2(acc[3]);
        float a = sm->vb0[j] + t1 * sm->vW0c[j]
                + ((s0.x + s0.y) + (s1.x + s1.y))
                + ((s2.x + s2.y) + (s3.x + s3.y));
        sm->z1[bb][j] = lipswish_f(a);
    }
    __syncthreads();

    // ---- layer 2: (128 -> 128), paired ----
    {
        const u64* wp = (const u64*)&sm->vW1[j * 130];
        const u64* zp = (const u64*)sm->z1[bb];
        u64 acc[4] = {0ull, 0ull, 0ull, 0ull};
        #pragma unroll
        for (int p = 0; p < 64; p++) ffma2(acc[p & 3], wp[p], zp[p]);
        float2 s0 = unpack2(acc[0]), s1 = unpack2(acc[1]);
        float2 s2 = unpack2(acc[2]), s3 = unpack2(acc[3]);
        float a = sm->vb1[j]
                + ((s0.x + s0.y) + (s1.x + s1.y))
                + ((s2.x + s2.y) + (s3.x + s3.y));
        float v = lipswish_f(a);
        sm->z2[bb][j]  = v;            // for tail
        sm->z2d[j][bb] = pack2(v, v);  // pre-duplicated for main loop
    }
    __syncthreads();

    // ---- layer 3 main: outputs [0, 2048), 8 per thread x 2 batches (R6 form) ----
    {
        u64 acc[8];   // [b0: wa01, wa23, wb01, wb23 | b1: same]
        #pragma unroll
        for (int i = 0; i < 8; i++) acc[i] = 0ull;

        #pragma unroll 2
        for (int kk = 0; kk < 32; kk++) {
            #pragma unroll
            for (int u = 0; u < 4; u++) {
                const int k = 4 * kk + u;
                const float* wrow = g_vW2T + (size_t)k * O_MAIN;
                ulonglong2 wa = *(const ulonglong2*)(wrow + 4 * tid);
                ulonglong2 wb = *(const ulonglong2*)(wrow + 4 * tid + 1024);
                u64 zz0 = sm->z2d[k][0];   // broadcast LDS.64, pre-duplicated
                u64 zz1 = sm->z2d[k][1];
                ffma2(acc[0], wa.x, zz0); ffma2(acc[1], wa.y, zz0);
                ffma2(acc[2], wb.x, zz0); ffma2(acc[3], wb.y, zz0);
                ffma2(acc[4], wa.x, zz1); ffma2(acc[5], wa.y, zz1);
                ffma2(acc[6], wb.x, zz1); ffma2(acc[7], wb.y, zz1);
            }
        }
        // epilogue: bias + tanh + store
        {
            int oa = 4 * tid, ob = 4 * tid + 1024;
            float2 r;
            r = unpack2(acc[0]);
            sm->vbuf[0][oa + 0] = tanh_f(r.x + sm->vb2[oa + 0]);
            sm->vbuf[0][oa + 1] = tanh_f(r.y + sm->vb2[oa + 1]);
            r = unpack2(acc[1]);
            sm->vbuf[0][oa + 2] = tanh_f(r.x + sm->vb2[oa + 2]);
            sm->vbuf[0][oa + 3] = tanh_f(r.y + sm->vb2[oa + 3]);
            r = unpack2(acc[2]);
            sm->vbuf[0][ob + 0] = tanh_f(r.x + sm->vb2[ob + 0]);
            sm->vbuf[0][ob + 1] = tanh_f(r.y + sm->vb2[ob + 1]);
            r = unpack2(acc[3]);
            sm->vbuf[0][ob + 2] = tanh_f(r.x + sm->vb2[ob + 2]);
            sm->vbuf[0][ob + 3] = tanh_f(r.y + sm->vb2[ob + 3]);
            r = unpack2(acc[4]);
            sm->vbuf[1][oa + 0] = tanh_f(r.x + sm->vb2[oa + 0]);
            sm->vbuf[1][oa + 1] = tanh_f(r.y + sm->vb2[oa + 1]);
            r = unpack2(acc[5]);
            sm->vbuf[1][oa + 2] = tanh_f(r.x + sm->vb2[oa + 2]);
            sm->vbuf[1][oa + 3] = tanh_f(r.y + sm->vb2[oa + 3]);
            r = unpack2(acc[6]);
            sm->vbuf[1][ob + 0] = tanh_f(r.x + sm->vb2[ob + 0]);
            sm->vbuf[1][ob + 1] = tanh_f(r.y + sm->vb2[ob + 1]);
            r = unpack2(acc[7]);
            sm->vbuf[1][ob + 2] = tanh_f(r.x + sm->vb2[ob + 2]);
            sm->vbuf[1][ob + 3] = tanh_f(r.y + sm->vb2[ob + 3]);
        }
    }

    // ---- layer 3 tail: outputs [2048, 2112), warp-per-output reduction over original vW2 ----
    {
        const int w = tid >> 5, lane = tid & 31;
        float4 zz0 = *(const float4*)&sm->z2[0][4 * lane];
        float4 zz1 = *(const float4*)&sm->z2[1][4 * lane];
        #pragma unroll
        for (int i = 0; i < 8; i++) {
            int o = O_MAIN + w * 8 + i;
            float4 wv = *(const float4*)(vW2 + (size_t)o * W_DIM + 4 * lane);
            float a0 = wv.x * zz0.x + wv.y * zz0.y + wv.z * zz0.z + wv.w * zz0.w;
            float a1 = wv.x * zz1.x + wv.y * zz1.y + wv.z * zz1.z + wv.w * zz1.w;
            #pragma unroll
            for (int off = 16; off; off >>= 1) {
                a0 += __shfl_xor_sync(0xffffffffu, a0, off);
                a1 += __shfl_xor_sync(0xffffffffu, a1, off);
            }
            if (lane == 0) {
                float b = sm->vb2[o];
                sm->vbuf[0][o] = tanh_f(a0 + b);
                sm->vbuf[1][o] = tanh_f(a1 + b);
            }
        }
    }
    __syncthreads();
}

__global__ void __launch_bounds__(NTHR, 1) cde_kernel(
    const float* __restrict__ ts,  const float* __restrict__ ys,
    const float* __restrict__ iW0, const float* __restrict__ ib0,
    const float* __restrict__ iW1, const float* __restrict__ ib1,
    const float* __restrict__ iW2, const float* __restrict__ ib2,
    const float* __restrict__ vW0, const float* __restrict__ vb0,
    const float* __restrict__ vW1, const float* __restrict__ vb1,
    const float* __restrict__ vW2, const float* __restrict__ vb2,
    const float* __restrict__ rW,  const float* __restrict__ rb,
    float* __restrict__ out)
{
    extern __shared__ float smraw[];
    Smem* sm = reinterpret_cast<Smem*>(smraw);
    const int tid = threadIdx.x;
    const int b0  = blockIdx.x * BA;

    // ---- stage weights into smem ----
    for (int i = tid; i < W_DIM * 65; i += NTHR) {
        int j = i / 65, c = i % 65;
        if (c == 0) sm->vW0c[j] = vW0[i];
        else        sm->vW0p[j * 66 + (c - 1)] = vW0[i];
    }
    for (int i = tid; i < W_DIM * W_DIM; i += NTHR) {
        int j = i >> 7, k = i & 127;
        sm->vW1[j * 130 + k] = vW1[i];
    }
    if (tid < W_DIM) { sm->vb0[tid] = vb0[tid]; sm->vb1[tid] = vb1[tid]; }
    for (int i = tid; i < O_DIM; i += NTHR) sm->vb2[i] = vb2[i];

    // dx-owner thread mapping (valid when tid < BA*C_DIM = 66)
    const int myb = tid / C_DIM;
    const int myc = tid - myb * C_DIM;
    const bool dxo = (tid < BA * C_DIM);

    // initial x0 = [ts[0], ys[b,0,:]] into dxv[0]; cury lives in a register
    float cury_r = 0.f, pref_y = 0.f;
    if (dxo) {
        if (myc == 0) {
            sm->dxv[0][myb][0] = ts[0];
        } else {
            float v0 = ys[(size_t)(b0 + myb) * T_LEN * D_IN + (myc - 1)];
            sm->dxv[0][myb][myc] = v0;
            cury_r = v0;
            pref_y = __ldg(&ys[(size_t)(b0 + myb) * T_LEN * D_IN + D_IN + (myc - 1)]);  // t=1
        }
    }
    float pref_t = __ldg(&ts[1]);
    __syncthreads();

    // ---- initial MLP: relu(iW0 x + ib0) -> relu(iW1 . + ib1) -> iW2 . + ib2 ----
    {
        int bb = tid >> 7, j = tid & 127;
        float a = ib0[j];
        #pragma unroll
        for (int i = 0; i < C_DIM; i++) a += sm->dxv[0][bb][i] * iW0[j * C_DIM + i];
        sm->z1[bb][j] = fmaxf(a, 0.f);
    }
    __syncthreads();
    {
        int bb = tid >> 7, j = tid & 127;
        float a = ib1[j];
        #pragma unroll 8
        for (int k = 0; k < W_DIM; k++) a += sm->z1[bb][k] * iW1[j * W_DIM + k];
        sm->z2[bb][j] = fmaxf(a, 0.f);
    }
    __syncthreads();

    float y = 0.f, yhat = 0.f, sdot = 0.f;
    if (tid < BA * H_DIM) {
        int bb = tid >> 6, h = tid & 63;
        float a = ib2[h];
        #pragma unroll 8
        for (int k = 0; k < W_DIM; k++) a += sm->z2[bb][k] * iW2[h * W_DIM + k];
        y = a; yhat = a;
        sm->yhat1[bb][h] = a;
    }
    __syncthreads();

    // v0 = vf(ts[0], y0)
    vf_eval(sm, tid, ts[0], vW2);

    // ---- scan over 1023 steps ----
    float tprev = ts[0];
    for (int t = 1; t < T_LEN; t++) {
        const int par = t & 1;
        float t1 = pref_t;

        // dx = x[t] - x[t-1] into dxv[par] (prefetched values)
        if (dxo) {
            if (myc == 0) {
                sm->dxv[par][myb][0] = t1 - tprev;
            } else {
                float nv = pref_y;
                sm->dxv[par][myb][myc] = nv - cury_r;
                cury_r = nv;
            }
        }
        tprev = t1;

        // issue prefetch for step t+1 (covered by the rest of this step)
        if (t + 1 < T_LEN) {
            if (dxo && myc != 0)
                pref_y = __ldg(&ys[(size_t)(b0 + myb) * T_LEN * D_IN
                                   + (size_t)(t + 1) * D_IN + (myc - 1)]);
            pref_t = __ldg(&ts[t + 1]);
        }
        __syncthreads();

        // s = v . dx ; yhat1 = 2y - yhat + s
        if (tid < BA * H_DIM) {
            int bb = tid >> 6, h = tid & 63;
            const float* vp = &sm->vbuf[bb][h * C_DIM];
            const float* dp = sm->dxv[par][bb];
            float a = 0.f;
            #pragma unroll
            for (int c = 0; c < C_DIM; c++) a += vp[c] * dp[c];
            sdot = a;
            float yh1 = 2.f * y - yhat + a;
            yhat = yh1;
            sm->yhat1[bb][h] = yh1;
        }
        __syncthreads();

        // v1 = vf(t1, yhat1)  (overwrites vbuf; ends with __syncthreads)
        vf_eval(sm, tid, t1, vW2);

        // y += 0.5 * (s + v1 . dx)   — no trailing barrier (dxv parity-buffered)
        if (tid < BA * H_DIM) {
            int bb = tid >> 6, h = tid & 63;
            const float* vp = &sm->vbuf[bb][h * C_DIM];
            const float* dp = sm->dxv[par][bb];
            float a = 0.f;
            #pragma unroll
            for (int c = 0; c < C_DIM; c++) a += vp[c] * dp[c];
            y += 0.5f * (sdot + a);
        }
    }

    // ---- readout: out[b] = y . rW + rb ----
    __syncthreads();
    if (tid < BA * H_DIM) {
        int bb = tid >> 6, h = tid & 63;
        sm->red[bb][h] = y * rW[h];
    }
    __syncthreads();
    if (tid < BA) {
        float a = rb[0];
        #pragma unroll
        for (int h = 0; h < H_DIM; h++) a += sm->red[tid][h];
        out[b0 + tid] = a;
    }
}

extern "C" void kernel_launch(void* const* d_in, const int* in_sizes, int n_in,
                              void* d_out, int out_size) {
    (void)in_sizes; (void)n_in; (void)out_size;
    const float* ts  = (const float*)d_in[0];
    const float* ys  = (const float*)d_in[1];
    const float* iW0 = (const float*)d_in[2];
    const float* ib0 = (const float*)d_in[3];
    const float* iW1 = (const float*)d_in[4];
    const float* ib1 = (const float*)d_in[5];
    const float* iW2 = (const float*)d_in[6];
    const float* ib2 = (const float*)d_in[7];
    const float* vW0 = (const float*)d_in[8];
    const float* vb0 = (const float*)d_in[9];
    const float* vW1 = (const float*)d_in[10];
    const float* vb1 = (const float*)d_in[11];
    const float* vW2 = (const float*)d_in[12];
    const float* vb2 = (const float*)d_in[13];
    const float* rW  = (const float*)d_in[14];
    const float* rb  = (const float*)d_in[15];
    float* out = (float*)d_out;

    cudaFuncSetAttribute(cde_kernel, cudaFuncAttributeMaxDynamicSharedMemorySize,
                         (int)sizeof(Smem));

    cde_transpose_kernel<<<(W_DIM * O_MAIN + 255) / 256, 256>>>(vW2);
    cde_kernel<<<NCTA, NTHR, sizeof(Smem)>>>(
        ts, ys, iW0, ib0, iW1, ib1, iW2, ib2,
        vW0, vb0, vW1, vb1, vW2, vb2, rW, rb, out);
}